// round 1
// baseline (speedup 1.0000x reference)
#include <cuda_runtime.h>

// YOLO loss: pred/target (bs, 7, 7, 30) f32 -> scalar f32.
// Streaming reduction, HBM-bound. Strategy: smem-staged coalesced tile loads,
// per-cell compute from smem, hierarchical reduction into a double accumulator.

#define S_GRID 7
#define CH 30
#define CELLS_PER_BLOCK 128
#define NTHREADS 128

__device__ double g_acc;

__global__ void zero_acc_kernel() {
    g_acc = 0.0;
}

__global__ __launch_bounds__(NTHREADS) void yolo_loss_kernel(
    const float* __restrict__ pred,
    const float* __restrict__ targ,
    int total_cells)
{
    __shared__ float sp[CELLS_PER_BLOCK * CH];   // 15360 B
    __shared__ float st[CELLS_PER_BLOCK * CH];   // 15360 B
    __shared__ float warp_sums[NTHREADS / 32];

    const int tid = threadIdx.x;
    const long long cell0 = (long long)blockIdx.x * CELLS_PER_BLOCK;
    int ncells = total_cells - (int)cell0;
    if (ncells > CELLS_PER_BLOCK) ncells = CELLS_PER_BLOCK;

    const float* gpb = pred + cell0 * CH;
    const float* gtb = targ + cell0 * CH;

    if (ncells == CELLS_PER_BLOCK) {
        // Full tile: coalesced float4 staging (base offset is 15360B-aligned).
        const float4* p4 = (const float4*)gpb;
        const float4* t4 = (const float4*)gtb;
        float4* sp4 = (float4*)sp;
        float4* st4 = (float4*)st;
        constexpr int NV4 = CELLS_PER_BLOCK * CH / 4;  // 960
        #pragma unroll
        for (int i = tid; i < NV4; i += NTHREADS) {
            sp4[i] = p4[i];
            st4[i] = t4[i];
        }
    } else {
        // Tail tile (rare): scalar copy of valid region only.
        const int nfl = ncells * CH;
        for (int i = tid; i < nfl; i += NTHREADS) {
            sp[i] = gpb[i];
            st[i] = gtb[i];
        }
    }
    __syncthreads();

    float loss = 0.0f;
    if (tid < ncells) {
        const float* p = sp + tid * CH;
        const float* t = st + tid * CH;

        const float obj = (t[4] > 0.0f) ? 1.0f : 0.0f;

        // no-object confidence loss (both conf channels: 4 and 9)
        const float dn0 = p[4] - t[4];
        const float dn1 = p[9] - t[9];
        const float noobj = dn0 * dn0 + dn1 * dn1;

        // class loss (channels 10..29)
        float cls = 0.0f;
        #pragma unroll
        for (int k = 10; k < 30; k++) {
            const float d = p[k] - t[k];
            cls = fmaf(d, d, cls);
        }

        // Target box 0 in xyxy (xy scaled by 1/S, wh raw)
        const float invS = 1.0f / (float)S_GRID;
        const float tx = t[0] * invS, ty = t[1] * invS;
        const float tw = t[2], th = t[3];
        const float tx0 = tx - 0.5f * tw, tx1 = tx + 0.5f * tw;
        const float ty0 = ty - 0.5f * th, ty1 = ty + 0.5f * th;
        const float area_t = tw * th;

        float iou0 = 0.0f, iou1 = 0.0f;
        #pragma unroll
        for (int b = 0; b < 2; b++) {
            const float* q = p + 5 * b;
            const float px = q[0] * invS, py = q[1] * invS;
            const float pw = q[2], ph = q[3];
            const float lx = fmaxf(px - 0.5f * pw, tx0);
            const float rx = fminf(px + 0.5f * pw, tx1);
            const float ly = fmaxf(py - 0.5f * ph, ty0);
            const float ry = fminf(py + 0.5f * ph, ty1);
            const float wx = fmaxf(rx - lx, 0.0f);
            const float wy = fmaxf(ry - ly, 0.0f);
            const float inter = wx * wy;
            const float uni = fmaxf(pw * ph + area_t - inter, 1e-10f);
            const float iou = inter / uni;
            if (b == 0) iou0 = iou; else iou1 = iou;
        }
        // jnp.argmax picks the first max -> b=1 only on strict greater.
        const int rb = (iou1 > iou0) ? 1 : 0;
        const float miou = fmaxf(iou0, iou1);

        const float* q  = p + 5 * rb;
        const float* tq = t + 5 * rb;
        const float dx = q[0] - tq[0];
        const float dy = q[1] - tq[1];
        const float lxy = dx * dx + dy * dy;
        const float dw = sqrtf(q[2]) - sqrtf(tq[2]);
        const float dh = sqrtf(q[3]) - sqrtf(tq[3]);
        const float lwh = dw * dw + dh * dh;
        const float dob = q[4] - miou;
        const float lobj = dob * dob;

        loss = obj * (5.0f * (lxy + lwh) + lobj + cls)
             + 0.5f * (1.0f - obj) * noobj;
    }

    // Warp reduce
    #pragma unroll
    for (int o = 16; o > 0; o >>= 1)
        loss += __shfl_xor_sync(0xffffffffu, loss, o);
    if ((tid & 31) == 0) warp_sums[tid >> 5] = loss;
    __syncthreads();
    if (tid == 0) {
        float bsum = warp_sums[0] + warp_sums[1] + warp_sums[2] + warp_sums[3];
        atomicAdd(&g_acc, (double)bsum);
    }
}

__global__ void finalize_kernel(float* __restrict__ out, double inv_bs) {
    out[0] = (float)(g_acc * inv_bs);
}

extern "C" void kernel_launch(void* const* d_in, const int* in_sizes, int n_in,
                              void* d_out, int out_size) {
    const float* pred = (const float*)d_in[0];
    const float* targ = (const float*)d_in[1];
    const long long n = (long long)in_sizes[0];
    const int total_cells = (int)(n / CH);               // bs * 49
    const int bs = total_cells / (S_GRID * S_GRID);
    const int grid = (total_cells + CELLS_PER_BLOCK - 1) / CELLS_PER_BLOCK;

    zero_acc_kernel<<<1, 1>>>();
    yolo_loss_kernel<<<grid, NTHREADS>>>(pred, targ, total_cells);
    finalize_kernel<<<1, 1>>>((float*)d_out, 1.0 / (double)bs);
}